// round 7
// baseline (speedup 1.0000x reference)
#include <cuda_runtime.h>
#include <math.h>

// Shapes (hardcoded from reference setup_inputs)
#define Bn   64
#define Nn   1025
#define Dn   1024
#define Cn   64
#define TOT  (Bn * Nn)   // 65600 rows, = 1025 * 64 exactly

// Scratch (device globals; no runtime allocation)
__device__ __align__(16) float g_h[(size_t)Bn * Nn * Cn];     // post LN+GEMM1   (B,N,C)
__device__ __align__(16) float g_sp[(size_t)Bn * 1024 * Cn];  // post depthwise  (B,HW,C)
__device__ __align__(16) float g_act[(size_t)Bn * Nn * Cn];   // post proj+gelu  (B,N,C)

// ---------- packed f32x2 helpers ----------
static __device__ __forceinline__ unsigned long long pk2(float a, float b) {
    unsigned long long r;
    asm("mov.b64 %0, {%1,%2};" : "=l"(r) : "f"(a), "f"(b));
    return r;
}
static __device__ __forceinline__ void upk2(unsigned long long v, float& a, float& b) {
    asm("mov.b64 {%0,%1}, %2;" : "=f"(a), "=f"(b) : "l"(v));
}
static __device__ __forceinline__ void fma2(unsigned long long& d, unsigned long long a,
                                            unsigned long long b) {
    asm("fma.rn.f32x2 %0, %1, %2, %0;" : "+l"(d) : "l"(a), "l"(b));
}

static __device__ __forceinline__ float gelu_exact(float t) {
    return 0.5f * t * (1.0f + erff(t * 0.70710678118654752f));
}

// ======================================================================
// Kernel 1: LN + gamma-mix + GEMM1 -> g_h
// 64 rows per block. K chunked by 128. smem: syd[128k][64r] dup ULL (64KB)
// + w1s[128k][64c] raw float (32KB) + stats (512B). K-split across 2 groups.
// ======================================================================
#define K1_SMEM (128*64*8 + 128*64*4 + 128*4)

__global__ __launch_bounds__(256, 2) void k1_ln_gemm1(
    const float* __restrict__ x, const float* __restrict__ lnw, const float* __restrict__ lnb,
    const float* __restrict__ gam, const float* __restrict__ gmx,
    const float* __restrict__ w1, const float* __restrict__ b1)
{
    extern __shared__ __align__(16) char sm[];
    unsigned long long* syd = (unsigned long long*)sm;            // [128][64]
    float* w1s = (float*)(sm + 128*64*8);                         // [128][64]
    float* smu = (float*)(sm + 128*64*8 + 128*64*4);              // [64]
    float* srs = smu + 64;                                        // [64]

    const int tid = threadIdx.x;
    const int row0 = blockIdx.x * 64;
    const int warp = tid >> 5, lane = tid & 31;

    // ---- LN stats: warp w handles rows warp*8..+7 (leaves rows L2-hot) ----
    for (int rr = 0; rr < 8; rr++) {
        int row = row0 + warp * 8 + rr;
        int b = row / Nn, n = row - b * Nn;
        const float4* p = (const float4*)(x + ((size_t)(n * Bn + b) << 10));
        float s = 0.f, q = 0.f;
#pragma unroll
        for (int i = 0; i < 8; i++) {
            float4 t = p[lane + 32 * i];
            s += t.x + t.y + t.z + t.w;
            q += t.x * t.x + t.y * t.y + t.z * t.z + t.w * t.w;
        }
#pragma unroll
        for (int o = 16; o; o >>= 1) {
            s += __shfl_xor_sync(0xffffffffu, s, o);
            q += __shfl_xor_sync(0xffffffffu, q, o);
        }
        if (lane == 0) {
            float mu = s * (1.0f / 1024.0f);
            float var = q * (1.0f / 1024.0f) - mu * mu;
            smu[warp * 8 + rr] = mu;
            srs[warp * 8 + rr] = rsqrtf(var + 1e-5f);
        }
    }
    __syncthreads();

    // production role: thread t -> row prow_l = t>>2, k-quarter pq = t&3
    const int prow_l = tid >> 2, pq = tid & 3;
    const int prow = row0 + prow_l;
    const int pb = prow / Nn, pn = prow - pb * Nn;
    const float* xrow = x + ((size_t)(pn * Bn + pb) << 10);
    const float pmu = smu[prow_l], prs = srs[prow_l];

    // GEMM role: kg = k-half, rg row-group (4 rows), cg col-group (8 cols)
    const int kg = tid >> 7;
    const int t2 = tid & 127;
    const int rg = t2 >> 3;
    const int cg = t2 & 7;

    unsigned long long acc[4][4];
#pragma unroll
    for (int r = 0; r < 4; r++)
#pragma unroll
        for (int p = 0; p < 4; p++) acc[r][p] = 0ull;

    for (int kc = 0; kc < 8; kc++) {
        const int kbase = kc * 128;
        __syncthreads();   // previous chunk's GEMM reads done before overwrite

        // ---- produce y chunk (LN fused), duplicated, transposed [k][row] ----
#pragma unroll
        for (int i = 0; i < 8; i++) {
            int kl = pq * 32 + i * 4;
            float4 xv = *(const float4*)(xrow + kbase + kl);
            int d4 = (kbase + kl) >> 2;
            float4 lw = ((const float4*)lnw)[d4];
            float4 lb = ((const float4*)lnb)[d4];
            float4 gm = ((const float4*)gam)[d4];
            float4 gx = ((const float4*)gmx)[d4];
            float y0 = ((xv.x - pmu) * prs * lw.x + lb.x) * gm.x + xv.x * gx.x;
            float y1 = ((xv.y - pmu) * prs * lw.y + lb.y) * gm.y + xv.y * gx.y;
            float y2 = ((xv.z - pmu) * prs * lw.z + lb.z) * gm.z + xv.z * gx.z;
            float y3 = ((xv.w - pmu) * prs * lw.w + lb.w) * gm.w + xv.w * gx.w;
            syd[(kl + 0) * 64 + prow_l] = pk2(y0, y0);
            syd[(kl + 1) * 64 + prow_l] = pk2(y1, y1);
            syd[(kl + 2) * 64 + prow_l] = pk2(y2, y2);
            syd[(kl + 3) * 64 + prow_l] = pk2(y3, y3);
        }
        // ---- load w1 chunk (contiguous 32KB) ----
        const float4* wsrc = (const float4*)(w1 + (size_t)kbase * 64);
#pragma unroll
        for (int i = 0; i < 8; i++)
            ((float4*)w1s)[tid + 256 * i] = wsrc[tid + 256 * i];
        __syncthreads();

        // ---- GEMM over this half's 64 k ----
        const unsigned long long* wu = (const unsigned long long*)w1s;  // [128][32]
        const int k0 = kg * 64;
#pragma unroll 4
        for (int kk = 0; kk < 64; kk++) {
            const int k = k0 + kk;
            ulonglong2 aA = *(const ulonglong2*)(syd + k * 64 + rg * 4);
            ulonglong2 aB = *(const ulonglong2*)(syd + k * 64 + rg * 4 + 2);
            ulonglong2 wA = *(const ulonglong2*)(wu + k * 32 + cg * 4);
            ulonglong2 wB = *(const ulonglong2*)(wu + k * 32 + cg * 4 + 2);
            fma2(acc[0][0], aA.x, wA.x); fma2(acc[0][1], aA.x, wA.y);
            fma2(acc[0][2], aA.x, wB.x); fma2(acc[0][3], aA.x, wB.y);
            fma2(acc[1][0], aA.y, wA.x); fma2(acc[1][1], aA.y, wA.y);
            fma2(acc[1][2], aA.y, wB.x); fma2(acc[1][3], aA.y, wB.y);
            fma2(acc[2][0], aB.x, wA.x); fma2(acc[2][1], aB.x, wA.y);
            fma2(acc[2][2], aB.x, wB.x); fma2(acc[2][3], aB.x, wB.y);
            fma2(acc[3][0], aB.y, wA.x); fma2(acc[3][1], aB.y, wA.y);
            fma2(acc[3][2], aB.y, wB.x); fma2(acc[3][3], aB.y, wB.y);
        }
    }

    // ---- combine k-halves and write ----
    __syncthreads();
    unsigned long long* red = syd;   // reuse (16KB needed)
    if (kg == 1) {
#pragma unroll
        for (int r = 0; r < 4; r++)
#pragma unroll
            for (int p = 0; p < 4; p++) red[t2 * 16 + r * 4 + p] = acc[r][p];
    }
    __syncthreads();
    if (kg == 0) {
        const int c0 = cg * 8;
        const float4 bl = *(const float4*)(b1 + c0);
        const float4 bh = *(const float4*)(b1 + c0 + 4);
#pragma unroll
        for (int r = 0; r < 4; r++) {
            float o_[8];
#pragma unroll
            for (int p = 0; p < 4; p++) {
                float a0, a1, b0v, b1v;
                upk2(acc[r][p], a0, a1);
                upk2(red[t2 * 16 + r * 4 + p], b0v, b1v);
                o_[2 * p] = a0 + b0v;
                o_[2 * p + 1] = a1 + b1v;
            }
            int row = row0 + rg * 4 + r;
            int b = row / Nn, n = row - b * Nn;
            float* dst = g_h + ((size_t)b * Nn + n) * 64 + c0;
            *(float4*)dst = make_float4(o_[0] + bl.x, o_[1] + bl.y, o_[2] + bl.z, o_[3] + bl.w);
            *(float4*)(dst + 4) = make_float4(o_[4] + bh.x, o_[5] + bh.y, o_[6] + bh.z, o_[7] + bh.w);
        }
    }
}

// ======================================================================
// Kernel 2: depthwise 3x3 + 5x5 + 7x7, averaged, + identity -> g_sp
// ======================================================================
__global__ __launch_bounds__(256) void k2_dwconv(
    const float* __restrict__ w3, const float* __restrict__ b3,
    const float* __restrict__ w5, const float* __restrict__ b5,
    const float* __restrict__ w7, const float* __restrict__ b7)
{
    __shared__ __align__(16) float tile[38 * 38 * 4];
    __shared__ float wk[4 * 83];

    const int tid = threadIdx.x;
    const int cg = blockIdx.x;
    const int b = blockIdx.y;

    for (int i = tid; i < 4 * 83; i += 256) {
        int ch = i / 83, j = i - ch * 83;
        int c = cg * 4 + ch;
        float wv;
        if (j < 9)       wv = w3[c * 9 + j];
        else if (j < 34) wv = w5[c * 25 + (j - 9)];
        else             wv = w7[c * 49 + (j - 34)];
        wk[i] = wv;
    }

    const float* src = g_h + ((size_t)b * Nn + 1) * 64 + cg * 4;
    for (int idx = tid; idx < 38 * 38; idx += 256) {
        int rr = idx / 38, cc = idx - rr * 38;
        int gy = rr - 3, gx = cc - 3;
        float4 val = make_float4(0.f, 0.f, 0.f, 0.f);
        if ((unsigned)gy < 32u && (unsigned)gx < 32u)
            val = *(const float4*)(src + (size_t)(gy * 32 + gx) * 64);
        *(float4*)&tile[idx * 4] = val;
    }
    __syncthreads();

    const int ch = tid & 3;
    const int col = (tid >> 2) & 31;
    const int row0 = (tid >> 7) * 16;

    float acc[16];
#pragma unroll
    for (int k = 0; k < 16; k++) acc[k] = 0.f;

    const float* wc = wk + ch * 83;

#define CONV_TAPS(RAD, WOFF, KS)                                                   \
    for (int dy = -(RAD); dy <= (RAD); dy++) {                                     \
        for (int dx = -(RAD); dx <= (RAD); dx++) {                                 \
            float wv = wc[(WOFF) + (dy + (RAD)) * (KS) + (dx + (RAD))];            \
            const float* tp = tile + (((row0 + 3 + dy) * 38) + (col + 3 + dx)) * 4 + ch; \
            _Pragma("unroll")                                                      \
            for (int k = 0; k < 16; k++) acc[k] += tp[k * 152] * wv;               \
        }                                                                          \
    }

    CONV_TAPS(1, 0, 3)
    CONV_TAPS(2, 9, 5)
    CONV_TAPS(3, 34, 7)
#undef CONV_TAPS

    const int c = cg * 4 + ch;
    const float bsum = (b3[c] + b5[c] + b7[c]) * (1.0f / 3.0f);
    float* dst = g_sp + ((size_t)b * 1024) * 64 + c;
    const float* ctr = tile + ((row0 + 3) * 38 + col + 3) * 4 + ch;
#pragma unroll
    for (int k = 0; k < 16; k++) {
        float o = acc[k] * (1.0f / 3.0f) + bsum + ctr[k * 152];
        dst[(size_t)((row0 + k) * 32 + col) * 64] = o;
    }
}

// ======================================================================
// Kernel 3: 1x1 proj + residual + exact GELU -> g_act (spatial tokens)
// ======================================================================
__global__ __launch_bounds__(256) void k3_proj_gelu(
    const float* __restrict__ pw, const float* __restrict__ pb)
{
    __shared__ float pws[64 * 65];
    __shared__ float ssp[32 * 64];

    const int tid = threadIdx.x;
    const int b = blockIdx.x >> 5;
    const int pbase = (blockIdx.x & 31) * 32;

    for (int i = tid; i < 4096; i += 256)
        pws[(i >> 6) * 65 + (i & 63)] = pw[i];

    const float* src = g_sp + ((size_t)b * 1024 + pbase) * 64;
    for (int i = tid; i < 2048; i += 256) ssp[i] = src[i];
    __syncthreads();

    const int c = tid & 63;
    const int pg = tid >> 6;
    float acc[8];
#pragma unroll
    for (int j = 0; j < 8; j++) acc[j] = 0.f;

    const float* wr = pws + c * 65;
    const float* sr = ssp + pg * 8 * 64;
#pragma unroll 8
    for (int k = 0; k < 64; k++) {
        float wv = wr[k];
#pragma unroll
        for (int j = 0; j < 8; j++) acc[j] += sr[j * 64 + k] * wv;
    }

    const float pbv = pb[c];
    float* dst = g_act + ((size_t)b * Nn + 1 + pbase + pg * 8) * 64 + c;
#pragma unroll
    for (int j = 0; j < 8; j++) {
        float t = sr[j * 64 + c] + acc[j] + pbv;
        dst[(size_t)j * 64] = gelu_exact(t);
    }
}

// CLS token: gelu only
__global__ void k_cls_gelu() {
    int i = blockIdx.x * 256 + threadIdx.x;
    if (i < Bn * Cn) {
        int b = i >> 6, c = i & 63;
        size_t off = (size_t)b * Nn * 64 + c;
        g_act[off] = gelu_exact(g_h[off]);
    }
}

// ======================================================================
// Kernel 4: GEMM2 (g_act @ w2 + b2) + residual x -> out
// 64 rows x 128 cols per block. smem: w2s 32KB + dup'd act 32KB.
// ======================================================================
#define K4_SMEM (64*128*4 + 64*64*8)

__global__ __launch_bounds__(256, 2) void k4_gemm2(
    const float* __restrict__ x, const float* __restrict__ w2,
    const float* __restrict__ b2, float* __restrict__ out)
{
    extern __shared__ __align__(16) char sm[];
    float* w2s = (float*)sm;                                      // [64][128]
    unsigned long long* sga = (unsigned long long*)(sm + 64*128*4); // [64k][64r]

    const int tid = threadIdx.x;
    const int row0 = (blockIdx.x >> 3) * 64;
    const int co = (blockIdx.x & 7) * 128;

    // ---- load w2 tile: 64 k-rows x 128 cols ----
#pragma unroll
    for (int i = 0; i < 8; i++) {
        int idx = tid + 256 * i;        // float4 index, 2048 total
        int k = idx >> 5, c4 = idx & 31;
        ((float4*)w2s)[idx] = *(const float4*)(w2 + (size_t)k * 1024 + co + c4 * 4);
    }
    // ---- load act rows duplicated, transposed [k][row] ----
    {
        const int r = tid >> 2, q = tid & 3;
        int grow = row0 + r;
        int gb = grow / Nn, gn = grow - gb * Nn;
        const float4* gp = (const float4*)(g_act + ((size_t)gb * Nn + gn) * 64 + q * 16);
#pragma unroll
        for (int i = 0; i < 4; i++) {
            float4 g = gp[i];
            int k0 = q * 16 + i * 4;
            sga[(k0 + 0) * 64 + r] = pk2(g.x, g.x);
            sga[(k0 + 1) * 64 + r] = pk2(g.y, g.y);
            sga[(k0 + 2) * 64 + r] = pk2(g.z, g.z);
            sga[(k0 + 3) * 64 + r] = pk2(g.w, g.w);
        }
    }
    __syncthreads();

    // ---- GEMM: thread = 8 rows (rg) x 4 cols (cw) ----
    const int rg = tid >> 5;    // rows rg*8..+7
    const int cw = tid & 31;    // cols cw*4..+3 (2 ULL pairs)
    unsigned long long acc[8][2];
#pragma unroll
    for (int r = 0; r < 8; r++) { acc[r][0] = 0ull; acc[r][1] = 0ull; }

    const unsigned long long* wu = (const unsigned long long*)w2s;  // [64][64]
#pragma unroll 4
    for (int k = 0; k < 64; k++) {
        ulonglong2 aA = *(const ulonglong2*)(sga + (k << 6) + (rg << 3));
        ulonglong2 aB = *(const ulonglong2*)(sga + (k << 6) + (rg << 3) + 2);
        ulonglong2 aC = *(const ulonglong2*)(sga + (k << 6) + (rg << 3) + 4);
        ulonglong2 aD = *(const ulonglong2*)(sga + (k << 6) + (rg << 3) + 6);
        ulonglong2 wv = *(const ulonglong2*)(wu + (k << 6) + (cw << 1));
        fma2(acc[0][0], aA.x, wv.x); fma2(acc[0][1], aA.x, wv.y);
        fma2(acc[1][0], aA.y, wv.x); fma2(acc[1][1], aA.y, wv.y);
        fma2(acc[2][0], aB.x, wv.x); fma2(acc[2][1], aB.x, wv.y);
        fma2(acc[3][0], aB.y, wv.x); fma2(acc[3][1], aB.y, wv.y);
        fma2(acc[4][0], aC.x, wv.x); fma2(acc[4][1], aC.x, wv.y);
        fma2(acc[5][0], aC.y, wv.x); fma2(acc[5][1], aC.y, wv.y);
        fma2(acc[6][0], aD.x, wv.x); fma2(acc[6][1], aD.x, wv.y);
        fma2(acc[7][0], aD.y, wv.x); fma2(acc[7][1], aD.y, wv.y);
    }

    // ---- epilogue: + b2 + x residual -> out (N,B,D) ----
    const int c0 = co + cw * 4;
    const float4 bv = *(const float4*)(b2 + c0);
#pragma unroll
    for (int r = 0; r < 8; r++) {
        int row = row0 + rg * 8 + r;
        int b = row / Nn, n = row - b * Nn;
        size_t off = ((size_t)(n * Bn + b) << 10) + c0;
        float4 xv = *(const float4*)(x + off);
        float a0, a1, a2, a3;
        upk2(acc[r][0], a0, a1);
        upk2(acc[r][1], a2, a3);
        *(float4*)(out + off) = make_float4(xv.x + bv.x + a0, xv.y + bv.y + a1,
                                            xv.z + bv.z + a2, xv.w + bv.w + a3);
    }
}

// ======================================================================
extern "C" void kernel_launch(void* const* d_in, const int* in_sizes, int n_in,
                              void* d_out, int out_size)
{
    (void)in_sizes; (void)n_in; (void)out_size;
    const float* x     = (const float*)d_in[0];
    const float* ln_w  = (const float*)d_in[1];
    const float* ln_b  = (const float*)d_in[2];
    const float* gamma = (const float*)d_in[3];
    const float* gmx   = (const float*)d_in[4];
    const float* w1    = (const float*)d_in[5];
    const float* b1    = (const float*)d_in[6];
    const float* w2    = (const float*)d_in[7];
    const float* b2    = (const float*)d_in[8];
    const float* dw3w  = (const float*)d_in[9];
    const float* dw3b  = (const float*)d_in[10];
    const float* dw5w  = (const float*)d_in[11];
    const float* dw5b  = (const float*)d_in[12];
    const float* dw7w  = (const float*)d_in[13];
    const float* dw7b  = (const float*)d_in[14];
    const float* projw = (const float*)d_in[15];
    const float* projb = (const float*)d_in[16];
    float* out = (float*)d_out;

    cudaFuncSetAttribute(k1_ln_gemm1, cudaFuncAttributeMaxDynamicSharedMemorySize, K1_SMEM);
    cudaFuncSetAttribute(k4_gemm2,    cudaFuncAttributeMaxDynamicSharedMemorySize, K4_SMEM);

    k1_ln_gemm1<<<1025, 256, K1_SMEM>>>(x, ln_w, ln_b, gamma, gmx, w1, b1);
    k2_dwconv<<<dim3(16, 64), 256>>>(dw3w, dw3b, dw5w, dw5b, dw7w, dw7b);
    k_cls_gelu<<<16, 256>>>();
    k3_proj_gelu<<<2048, 256>>>(projw, projb);
    k4_gemm2<<<8200, 256, K4_SMEM>>>(x, w2, b2, out);
}

// round 10
// speedup vs baseline: 1.4923x; 1.4923x over previous
#include <cuda_runtime.h>
#include <math.h>

// Shapes (hardcoded from reference setup_inputs)
#define Bn   64
#define Nn   1025
#define Dn   1024
#define Cn   64
#define TOT  (Bn * Nn)   // 65600 rows = 8200 * 8 = 128.125 * 512

// Scratch (device globals; no runtime allocation)
__device__ __align__(16) float g_h[(size_t)Bn * Nn * Cn];     // post LN+GEMM1   (B,N,C)
__device__ __align__(16) float g_sp[(size_t)Bn * 1024 * Cn];  // post depthwise  (B,HW,C)
__device__ __align__(16) float g_act[(size_t)Bn * Nn * Cn];   // post proj+gelu  (B,N,C)

// ---------- packed f32x2 helpers ----------
static __device__ __forceinline__ unsigned long long pk2(float a, float b) {
    unsigned long long r;
    asm("mov.b64 %0, {%1,%2};" : "=l"(r) : "f"(a), "f"(b));
    return r;
}
static __device__ __forceinline__ void upk2(unsigned long long v, float& a, float& b) {
    asm("mov.b64 {%0,%1}, %2;" : "=f"(a), "=f"(b) : "l"(v));
}
static __device__ __forceinline__ void fma2(unsigned long long& d, unsigned long long a,
                                            unsigned long long b) {
    asm("fma.rn.f32x2 %0, %1, %2, %0;" : "+l"(d) : "l"(a), "l"(b));
}

static __device__ __forceinline__ float gelu_exact(float t) {
    return 0.5f * t * (1.0f + erff(t * 0.70710678118654752f));
}

// ======================================================================
// Kernel 1: LayerNorm + gamma-mix + GEMM1 (y @ w1 + b1) -> g_h
// 8 rows per block (R5 structure scaled). Single produce phase, single
// GEMM phase. smem: syd[8 rows][1024 k] duplicated ULL (64KB, dynamic),
// reused as fp32 reduction buffer.
// ======================================================================
#define K1_SMEM (8 * 1024 * 8)

__global__ __launch_bounds__(256, 2) void k1_ln_gemm1(
    const float* __restrict__ x, const float* __restrict__ lnw, const float* __restrict__ lnb,
    const float* __restrict__ gam, const float* __restrict__ gmx,
    const float* __restrict__ w1, const float* __restrict__ b1)
{
    extern __shared__ __align__(16) char sm1[];
    unsigned long long* syd = (unsigned long long*)sm1;   // [8][1024]
    __shared__ float2 red8[8][8];

    const int tid = threadIdx.x;
    const int row0 = blockIdx.x * 8;

    int bb[8], nn[8];
#pragma unroll
    for (int r = 0; r < 8; r++) {
        int row = row0 + r;
        bb[r] = row / Nn;
        nn[r] = row - bb[r] * Nn;
    }

    // ---- load x rows (each thread: d-slice tid*4..+3 of all 8 rows) ----
    float4 v[8];
    float s[8], q[8];
#pragma unroll
    for (int r = 0; r < 8; r++) {
        const float4* p = (const float4*)(x + ((size_t)(nn[r] * Bn + bb[r]) << 10));
        float4 t = p[tid];
        v[r] = t;
        s[r] = t.x + t.y + t.z + t.w;
        q[r] = t.x * t.x + t.y * t.y + t.z * t.z + t.w * t.w;
    }
#pragma unroll
    for (int o = 16; o; o >>= 1) {
#pragma unroll
        for (int r = 0; r < 8; r++) {
            s[r] += __shfl_xor_sync(0xffffffffu, s[r], o);
            q[r] += __shfl_xor_sync(0xffffffffu, q[r], o);
        }
    }
    const int wid = tid >> 5;
    if ((tid & 31) == 0) {
#pragma unroll
        for (int r = 0; r < 8; r++) red8[r][wid] = make_float2(s[r], q[r]);
    }
    __syncthreads();

    float mu[8], rs[8];
#pragma unroll
    for (int r = 0; r < 8; r++) {
        float a = 0.f, c = 0.f;
#pragma unroll
        for (int w = 0; w < 8; w++) { a += red8[r][w].x; c += red8[r][w].y; }
        mu[r] = a * (1.0f / 1024.0f);
        float var = c * (1.0f / 1024.0f) - mu[r] * mu[r];
        rs[r] = rsqrtf(var + 1e-5f);
    }

    // ---- y = (ln*gamma) + x*gammax, duplicated, layout [row][k] ----
    const float4 lw = ((const float4*)lnw)[tid];
    const float4 lb = ((const float4*)lnb)[tid];
    const float4 gm = ((const float4*)gam)[tid];
    const float4 gx = ((const float4*)gmx)[tid];
#pragma unroll
    for (int r = 0; r < 8; r++) {
        float4 t = v[r];
        float y0 = ((t.x - mu[r]) * rs[r] * lw.x + lb.x) * gm.x + t.x * gx.x;
        float y1 = ((t.y - mu[r]) * rs[r] * lw.y + lb.y) * gm.y + t.y * gx.y;
        float y2 = ((t.z - mu[r]) * rs[r] * lw.z + lb.z) * gm.z + t.z * gx.z;
        float y3 = ((t.w - mu[r]) * rs[r] * lw.w + lb.w) * gm.w + t.w * gx.w;
        unsigned long long* dst = syd + r * 1024 + tid * 4;
        dst[0] = pk2(y0, y0);
        dst[1] = pk2(y1, y1);
        dst[2] = pk2(y2, y2);
        dst[3] = pk2(y3, y3);
    }
    __syncthreads();

    // ---- GEMM: thread = (kgroup of 64 d) x (4 cols) x 8 rows ----
    const int gidx = tid >> 4;       // 0..15 -> d in [gidx*64, +64)
    const int cq = tid & 15;         // cols cq*4..+3
    const int c0 = cq * 4;
    unsigned long long acc[8][2];
#pragma unroll
    for (int r = 0; r < 8; r++) { acc[r][0] = 0ull; acc[r][1] = 0ull; }

    const float4* w1p = (const float4*)w1;
    const int dbase = gidx * 64;
#pragma unroll 4
    for (int dd = 0; dd < 64; dd++) {
        int d = dbase + dd;
        float4 w = w1p[d * 16 + cq];
        unsigned long long wl = pk2(w.x, w.y), wh = pk2(w.z, w.w);
#pragma unroll
        for (int r = 0; r < 8; r++) {
            unsigned long long yy = syd[r * 1024 + d];
            fma2(acc[r][0], yy, wl);
            fma2(acc[r][1], yy, wh);
        }
    }
    __syncthreads();

    // ---- cross-kgroup reduction (reuse syd as float buffer, 32KB) ----
    float* red = (float*)syd;   // [16 groups][8 rows][64 c]
#pragma unroll
    for (int r = 0; r < 8; r++) {
        float a0, a1, a2, a3;
        upk2(acc[r][0], a0, a1);
        upk2(acc[r][1], a2, a3);
        *(float4*)(red + (gidx * 512 + r * 64 + c0)) = make_float4(a0, a1, a2, a3);
    }
    __syncthreads();

#pragma unroll
    for (int h = 0; h < 2; h++) {
        int o = h * 256 + tid;          // 0..511
        int r = o >> 6, c = o & 63;
        float sum = b1[c];
#pragma unroll
        for (int g = 0; g < 16; g++) sum += red[g * 512 + o];
        g_h[((size_t)bb[r] * Nn + nn[r]) * 64 + c] = sum;
    }
}

// ======================================================================
// Kernel 2: depthwise 3x3 + 5x5 + 7x7, averaged, + identity -> g_sp
// ======================================================================
__global__ __launch_bounds__(256) void k2_dwconv(
    const float* __restrict__ w3, const float* __restrict__ b3,
    const float* __restrict__ w5, const float* __restrict__ b5,
    const float* __restrict__ w7, const float* __restrict__ b7)
{
    __shared__ __align__(16) float tile[38 * 38 * 4];
    __shared__ float wk[4 * 83];

    const int tid = threadIdx.x;
    const int cg = blockIdx.x;
    const int b = blockIdx.y;

    for (int i = tid; i < 4 * 83; i += 256) {
        int ch = i / 83, j = i - ch * 83;
        int c = cg * 4 + ch;
        float wv;
        if (j < 9)       wv = w3[c * 9 + j];
        else if (j < 34) wv = w5[c * 25 + (j - 9)];
        else             wv = w7[c * 49 + (j - 34)];
        wk[i] = wv;
    }

    const float* src = g_h + ((size_t)b * Nn + 1) * 64 + cg * 4;
    for (int idx = tid; idx < 38 * 38; idx += 256) {
        int rr = idx / 38, cc = idx - rr * 38;
        int gy = rr - 3, gx = cc - 3;
        float4 val = make_float4(0.f, 0.f, 0.f, 0.f);
        if ((unsigned)gy < 32u && (unsigned)gx < 32u)
            val = *(const float4*)(src + (size_t)(gy * 32 + gx) * 64);
        *(float4*)&tile[idx * 4] = val;
    }
    __syncthreads();

    const int ch = tid & 3;
    const int col = (tid >> 2) & 31;
    const int row0 = (tid >> 7) * 16;

    float acc[16];
#pragma unroll
    for (int k = 0; k < 16; k++) acc[k] = 0.f;

    const float* wc = wk + ch * 83;

#define CONV_TAPS(RAD, WOFF, KS)                                                   \
    for (int dy = -(RAD); dy <= (RAD); dy++) {                                     \
        for (int dx = -(RAD); dx <= (RAD); dx++) {                                 \
            float wv = wc[(WOFF) + (dy + (RAD)) * (KS) + (dx + (RAD))];            \
            const float* tp = tile + (((row0 + 3 + dy) * 38) + (col + 3 + dx)) * 4 + ch; \
            _Pragma("unroll")                                                      \
            for (int k = 0; k < 16; k++) acc[k] += tp[k * 152] * wv;               \
        }                                                                          \
    }

    CONV_TAPS(1, 0, 3)
    CONV_TAPS(2, 9, 5)
    CONV_TAPS(3, 34, 7)
#undef CONV_TAPS

    const int c = cg * 4 + ch;
    const float bsum = (b3[c] + b5[c] + b7[c]) * (1.0f / 3.0f);
    float* dst = g_sp + ((size_t)b * 1024) * 64 + c;
    const float* ctr = tile + ((row0 + 3) * 38 + col + 3) * 4 + ch;
#pragma unroll
    for (int k = 0; k < 16; k++) {
        float o = acc[k] * (1.0f / 3.0f) + bsum + ctr[k * 152];
        dst[(size_t)((row0 + k) * 32 + col) * 64] = o;
    }
}

// ======================================================================
// Kernel 3: 1x1 proj + residual + exact GELU -> g_act (spatial tokens)
// ======================================================================
__global__ __launch_bounds__(256) void k3_proj_gelu(
    const float* __restrict__ pw, const float* __restrict__ pb)
{
    __shared__ float pws[64 * 65];
    __shared__ float ssp[32 * 64];

    const int tid = threadIdx.x;
    const int b = blockIdx.x >> 5;
    const int pbase = (blockIdx.x & 31) * 32;

    for (int i = tid; i < 4096; i += 256)
        pws[(i >> 6) * 65 + (i & 63)] = pw[i];

    const float* src = g_sp + ((size_t)b * 1024 + pbase) * 64;
    for (int i = tid; i < 2048; i += 256) ssp[i] = src[i];
    __syncthreads();

    const int c = tid & 63;
    const int pg = tid >> 6;
    float acc[8];
#pragma unroll
    for (int j = 0; j < 8; j++) acc[j] = 0.f;

    const float* wr = pws + c * 65;
    const float* sr = ssp + pg * 8 * 64;
#pragma unroll 8
    for (int k = 0; k < 64; k++) {
        float wv = wr[k];
#pragma unroll
        for (int j = 0; j < 8; j++) acc[j] += sr[j * 64 + k] * wv;
    }

    const float pbv = pb[c];
    float* dst = g_act + ((size_t)b * Nn + 1 + pbase + pg * 8) * 64 + c;
#pragma unroll
    for (int j = 0; j < 8; j++) {
        float t = sr[j * 64 + c] + acc[j] + pbv;
        dst[(size_t)j * 64] = gelu_exact(t);
    }
}

// CLS token: gelu only
__global__ void k_cls_gelu() {
    int i = blockIdx.x * 256 + threadIdx.x;
    if (i < Bn * Cn) {
        int b = i >> 6, c = i & 63;
        size_t off = (size_t)b * Nn * 64 + c;
        g_act[off] = gelu_exact(g_h[off]);
    }
}

// ======================================================================
// Kernel 4: GEMM2 (g_act @ w2 + b2) + residual x -> out
// Block = 128-col chunk of w2 resident in smem (32KB, loaded ONCE),
// streams 512 rows in 8 subtiles of 64. Weight L2 traffic: 4.2GB -> 33MB.
// ======================================================================
#define K4_SMEM (64*128*4 + 64*64*4)

__global__ __launch_bounds__(256, 3) void k4_gemm2(
    const float* __restrict__ x, const float* __restrict__ w2,
    const float* __restrict__ b2, float* __restrict__ out)
{
    extern __shared__ __align__(16) char sm4[];
    float* w2s = (float*)sm4;                      // [64 k][128 c]
    float* sga = (float*)(sm4 + 64 * 128 * 4);     // [64 k][64 r] (rows natural pairs)

    const int tid = threadIdx.x;
    const int rb = blockIdx.x >> 3;                // row block (512 rows)
    const int co = (blockIdx.x & 7) * 128;         // col chunk
    const int rowbase = rb * 512;
    const int nsub = (TOT - rowbase < 512) ? ((TOT - rowbase) >> 6) : 8;

    // ---- load w2 chunk once: [64][128] ----
#pragma unroll
    for (int i = 0; i < 8; i++) {
        int f = tid + 256 * i;                      // float4 index, 2048 total
        int k = f >> 5, c4 = f & 31;
        ((float4*)w2s)[f] = *(const float4*)(w2 + (size_t)k * 1024 + co + c4 * 4);
    }

    const int rg = tid >> 5;        // warp id -> rows rg*8..+7 (uniform per warp)
    const int cw = tid & 31;        // cols cw*4..+3
    const int c0g = co + cw * 4;
    const float4 bv = *(const float4*)(b2 + c0g);

    const int lr = tid >> 2;        // load role: local row 0..63
    const int lq = tid & 3;         // k-quarter

    for (int s2 = 0; s2 < nsub; s2++) {
        __syncthreads();   // w2s ready (s2=0) / prev GEMM reads done

        // ---- load 64 act rows, transposed [k][r] ----
        {
            int row = rowbase + s2 * 64 + lr;
            int b = row / Nn, n = row - b * Nn;
            const float4* gp = (const float4*)(g_act + ((size_t)b * Nn + n) * 64 + lq * 16);
#pragma unroll
            for (int i = 0; i < 4; i++) {
                float4 g = gp[i];
                int k0 = lq * 16 + i * 4;
                sga[(k0 + 0) * 64 + lr] = g.x;
                sga[(k0 + 1) * 64 + lr] = g.y;
                sga[(k0 + 2) * 64 + lr] = g.z;
                sga[(k0 + 3) * 64 + lr] = g.w;
            }
        }
        __syncthreads();

        // ---- GEMM: 8 rows (4 natural pairs) x 4 cols ----
        unsigned long long acc[4][4];
#pragma unroll
        for (int p = 0; p < 4; p++)
#pragma unroll
            for (int j = 0; j < 4; j++) acc[p][j] = 0ull;

#pragma unroll 4
        for (int k = 0; k < 64; k++) {
            // y: 8 consecutive rows = 4 natural float2 pairs (broadcast per warp)
            ulonglong2 yA = *(const ulonglong2*)(sga + (k << 6) + (rg << 3));
            ulonglong2 yB = *(const ulonglong2*)(sga + (k << 6) + (rg << 3) + 4);
            float4 w = *(const float4*)(w2s + (k << 7) + (cw << 2));
            unsigned long long w0 = pk2(w.x, w.x), w1d = pk2(w.y, w.y);
            unsigned long long w2d = pk2(w.z, w.z), w3 = pk2(w.w, w.w);
            fma2(acc[0][0], yA.x, w0); fma2(acc[0][1], yA.x, w1d);
            fma2(acc[0][2], yA.x, w2d); fma2(acc[0][3], yA.x, w3);
            fma2(acc[1][0], yA.y, w0); fma2(acc[1][1], yA.y, w1d);
            fma2(acc[1][2], yA.y, w2d); fma2(acc[1][3], yA.y, w3);
            fma2(acc[2][0], yB.x, w0); fma2(acc[2][1], yB.x, w1d);
            fma2(acc[2][2], yB.x, w2d); fma2(acc[2][3], yB.x, w3);
            fma2(acc[3][0], yB.y, w0); fma2(acc[3][1], yB.y, w1d);
            fma2(acc[3][2], yB.y, w2d); fma2(acc[3][3], yB.y, w3);
        }

        // ---- epilogue: + b2 + x residual -> out (N,B,D layout) ----
#pragma unroll
        for (int p = 0; p < 4; p++) {
            int rowe = rowbase + s2 * 64 + rg * 8 + 2 * p;   // even row of pair
            float ae[4], ao[4];
#pragma unroll
            for (int j = 0; j < 4; j++) upk2(acc[p][j], ae[j], ao[j]);

            int b = rowe / Nn, n = rowe - b * Nn;
            size_t offe = ((size_t)(n * Bn + b) << 10) + c0g;
            float4 xe = *(const float4*)(x + offe);
            *(float4*)(out + offe) = make_float4(xe.x + bv.x + ae[0], xe.y + bv.y + ae[1],
                                                 xe.z + bv.z + ae[2], xe.w + bv.w + ae[3]);
            int rowo = rowe + 1;
            int b2i = rowo / Nn, n2 = rowo - b2i * Nn;
            size_t offo = ((size_t)(n2 * Bn + b2i) << 10) + c0g;
            float4 xo = *(const float4*)(x + offo);
            *(float4*)(out + offo) = make_float4(xo.x + bv.x + ao[0], xo.y + bv.y + ao[1],
                                                 xo.z + bv.z + ao[2], xo.w + bv.w + ao[3]);
        }
    }
}

// ======================================================================
extern "C" void kernel_launch(void* const* d_in, const int* in_sizes, int n_in,
                              void* d_out, int out_size)
{
    (void)in_sizes; (void)n_in; (void)out_size;
    const float* x     = (const float*)d_in[0];
    const float* ln_w  = (const float*)d_in[1];
    const float* ln_b  = (const float*)d_in[2];
    const float* gamma = (const float*)d_in[3];
    const float* gmx   = (const float*)d_in[4];
    const float* w1    = (const float*)d_in[5];
    const float* b1    = (const float*)d_in[6];
    const float* w2    = (const float*)d_in[7];
    const float* b2    = (const float*)d_in[8];
    const float* dw3w  = (const float*)d_in[9];
    const float* dw3b  = (const float*)d_in[10];
    const float* dw5w  = (const float*)d_in[11];
    const float* dw5b  = (const float*)d_in[12];
    const float* dw7w  = (const float*)d_in[13];
    const float* dw7b  = (const float*)d_in[14];
    const float* projw = (const float*)d_in[15];
    const float* projb = (const float*)d_in[16];
    float* out = (float*)d_out;

    cudaFuncSetAttribute(k1_ln_gemm1, cudaFuncAttributeMaxDynamicSharedMemorySize, K1_SMEM);
    cudaFuncSetAttribute(k4_gemm2,    cudaFuncAttributeMaxDynamicSharedMemorySize, K4_SMEM);

    k1_ln_gemm1<<<8200, 256, K1_SMEM>>>(x, ln_w, ln_b, gamma, gmx, w1, b1);
    k2_dwconv<<<dim3(16, 64), 256>>>(dw3w, dw3b, dw5w, dw5b, dw7w, dw7b);
    k_cls_gelu<<<16, 256>>>();
    k3_proj_gelu<<<2048, 256>>>(projw, projb);
    // 129 row-blocks of 512 rows (last has 64) x 8 col-chunks
    k4_gemm2<<<129 * 8, 256, K4_SMEM>>>(x, w2, b2, out);
}